// round 17
// baseline (speedup 1.0000x reference)
#include <cuda_runtime.h>
#include <cuda_fp16.h>
#include <cstdint>

// ---------------------------------------------------------------------------
// Problem constants
// ---------------------------------------------------------------------------
#define DIM      1024
#define N_HEADS  16
#define HEAD_DIM 64
#define BATCH    8
#define SEQ_L    1024
#define T_TOK    (BATCH * SEQ_L)     // 8192
#define HID      (4 * DIM)           // 4096
#define QKV_N    (3 * DIM)           // 3072
#define ADA_N    (6 * DIM)           // 6144
#define EPS_LN   1e-5f
#define LOG2E    1.44269504088896f

typedef __half  h16;
typedef __half2 h162;

// ---------------------------------------------------------------------------
// Scratch (__device__ globals; no allocations allowed)
// ---------------------------------------------------------------------------
__device__ float g_ada [BATCH * ADA_N];

// fp16 activations
__device__ __align__(16) h16 g_h   [T_TOK * DIM];      // LN+mod output
__device__ __align__(16) h16 g_qkv [(size_t)T_TOK * QKV_N];
__device__ __align__(16) h16 g_attn[T_TOK * DIM];
__device__ __align__(16) h16 g_mlp [T_TOK * HID];

// fp16 weights (single rounding; measured attenuation makes this safe)
__device__ __align__(16) h16 g_wqkv[DIM * QKV_N];
__device__ __align__(16) h16 g_wo  [DIM * DIM];
__device__ __align__(16) h16 g_w1  [DIM * HID];
__device__ __align__(16) h16 g_w2  [HID * DIM];

// ---------------------------------------------------------------------------
// Helpers
// ---------------------------------------------------------------------------
__device__ __forceinline__ float gelu_tanh(float x) {
    float x3 = x * x * x;
    return 0.5f * x * (1.0f + tanhf(0.7978845608028654f * (x + 0.044715f * x3)));
}

__device__ __forceinline__ void cp16(uint32_t saddr, const void* g) {
    asm volatile("cp.async.cg.shared.global [%0], [%1], 16;" :: "r"(saddr), "l"(g));
}

__device__ __forceinline__ void ldmA(uint32_t a[4], uint32_t addr) {
    asm volatile("ldmatrix.sync.aligned.m8n8.x4.shared.b16 {%0,%1,%2,%3}, [%4];"
                 : "=r"(a[0]), "=r"(a[1]), "=r"(a[2]), "=r"(a[3]) : "r"(addr));
}
__device__ __forceinline__ void ldmBt(uint32_t b[4], uint32_t addr) {
    asm volatile("ldmatrix.sync.aligned.m8n8.x4.trans.shared.b16 {%0,%1,%2,%3}, [%4];"
                 : "=r"(b[0]), "=r"(b[1]), "=r"(b[2]), "=r"(b[3]) : "r"(addr));
}
__device__ __forceinline__ void mma16816(float d[4], const uint32_t a[4],
                                         uint32_t b0, uint32_t b1) {
    asm volatile("mma.sync.aligned.m16n8k16.row.col.f32.f16.f16.f32 "
                 "{%0,%1,%2,%3}, {%4,%5,%6,%7}, {%8,%9}, {%0,%1,%2,%3};"
                 : "+f"(d[0]), "+f"(d[1]), "+f"(d[2]), "+f"(d[3])
                 : "r"(a[0]), "r"(a[1]), "r"(a[2]), "r"(a[3]), "r"(b0), "r"(b1));
}
__device__ __forceinline__ uint32_t packh(float lo, float hi) {
    h162 t = __floats2half2_rn(lo, hi);
    return *(uint32_t*)&t;
}

// ---------------------------------------------------------------------------
// Fused weight convert: all six fp32 weights -> fp16 in ONE launch.
// Block ranges: [0,3072) Wq/Wk/Wv -> concatenated qkv, [3072,4096) Wo,
// [4096,8192) W1, [8192,12288) W2.  1 block = 1024 float4 quads.
// ---------------------------------------------------------------------------
__global__ void conv_all(const float* __restrict__ Wq, const float* __restrict__ Wk,
                         const float* __restrict__ Wv, const float* __restrict__ Wo,
                         const float* __restrict__ W1, const float* __restrict__ W2,
                         h16* __restrict__ wqkv, h16* __restrict__ wo,
                         h16* __restrict__ w1, h16* __restrict__ w2)
{
    int bid = blockIdx.x;
    const float* src; h16* dst; int srcN, dstStride, col0, base;
    if (bid < 3072) {
        int wsel = bid >> 10;
        src = (wsel == 0) ? Wq : (wsel == 1) ? Wk : Wv;
        dst = wqkv; srcN = DIM; dstStride = QKV_N; col0 = wsel * DIM;
        base = bid & 1023;
    } else if (bid < 4096) {
        src = Wo; dst = wo; srcN = DIM; dstStride = DIM; col0 = 0; base = bid - 3072;
    } else if (bid < 8192) {
        src = W1; dst = w1; srcN = HID; dstStride = HID; col0 = 0; base = bid - 4096;
    } else {
        src = W2; dst = w2; srcN = DIM; dstStride = DIM; col0 = 0; base = bid - 8192;
    }
    int i = base * 256 + threadIdx.x;            // quad index
    float4 v = ((const float4*)src)[i];
    int e = i * 4;
    int k = e / srcN;
    int j = e - k * srcN;
    size_t d = (size_t)k * dstStride + col0 + j;
    *(h162*)&dst[d]     = __floats2half2_rn(v.x, v.y);
    *(h162*)&dst[d + 2] = __floats2half2_rn(v.z, v.w);
}

// ---------------------------------------------------------------------------
// adaLN GEMM (tiny: 8 x 1024 x 6144, fp32)
// ---------------------------------------------------------------------------
__global__ void ada_kernel(const float* __restrict__ c,
                           const float* __restrict__ W,
                           const float* __restrict__ bias,
                           float* __restrict__ out)
{
    __shared__ float cs[DIM];
    int b = blockIdx.y;
    int j = blockIdx.x * 256 + threadIdx.x;
    for (int i = threadIdx.x; i < DIM; i += 256) cs[i] = c[b * DIM + i];
    __syncthreads();
    float acc = bias[j];
#pragma unroll 8
    for (int k = 0; k < DIM; k++)
        acc += cs[k] * W[(size_t)k * ADA_N + j];
    out[b * ADA_N + j] = acc;
}

// ---------------------------------------------------------------------------
// Fused LayerNorm + adaLN modulation -> fp16 output
// ---------------------------------------------------------------------------
__global__ void ln_mod_kernel(const float* __restrict__ x,
                              const float* __restrict__ w,
                              const float* __restrict__ ada,
                              int sh_off, int sc_off,
                              h16* __restrict__ oh)
{
    int t   = blockIdx.x;
    int tid = threadIdx.x;
    const float* xr = x + (size_t)t * DIM;

    float xv[4];
    float s = 0.f, s2 = 0.f;
#pragma unroll
    for (int i = 0; i < 4; i++) {
        xv[i] = xr[tid + i * 256];
        s  += xv[i];
        s2 += xv[i] * xv[i];
    }
#pragma unroll
    for (int m = 16; m; m >>= 1) {
        s  += __shfl_xor_sync(0xffffffffu, s,  m);
        s2 += __shfl_xor_sync(0xffffffffu, s2, m);
    }
    __shared__ float red[2][8];
    int warp = tid >> 5, lane = tid & 31;
    if (lane == 0) { red[0][warp] = s; red[1][warp] = s2; }
    __syncthreads();
    float ts = 0.f, ts2 = 0.f;
#pragma unroll
    for (int i = 0; i < 8; i++) { ts += red[0][i]; ts2 += red[1][i]; }
    float mu   = ts  * (1.0f / DIM);
    float var  = ts2 * (1.0f / DIM) - mu * mu;
    float rstd = rsqrtf(var + EPS_LN);

    int b6 = (t >> 10) * ADA_N;
    size_t base = (size_t)t * DIM;
#pragma unroll
    for (int i = 0; i < 4; i++) {
        int c  = tid + i * 256;
        float g = (xv[i] - mu) * rstd * w[c];
        float o = g * (1.0f + ada[b6 + sc_off + c]) + ada[b6 + sh_off + c];
        oh[base + c] = __float2half_rn(o);
    }
}

// ---------------------------------------------------------------------------
// RoPE applied in place to the q,k columns of the fp16 qkv buffer.
// q pre-scaled by log2(e)/sqrt(HEAD_DIM). pos = t mod SEQ_L (structural).
// ---------------------------------------------------------------------------
__global__ void rope_kernel(h16* __restrict__ qkv,
                            const float* __restrict__ cosp,
                            const float* __restrict__ sinp)
{
    int idx = blockIdx.x * 256 + threadIdx.x;   // T * H * 32
    int t = idx >> 9;
    int r = idx & 511;
    int h = r >> 5;
    int d = r & 31;
    int pos = t & (SEQ_L - 1);
    float c = cosp[pos * 32 + d];
    float s = sinp[pos * 32 + d];
    size_t qb = (size_t)t * QKV_N + h * HEAD_DIM + d;
    size_t kb = qb + DIM;
    const float qs = 0.125f * LOG2E;

    float q1 = __half2float(qkv[qb]), q2 = __half2float(qkv[qb + 32]);
    qkv[qb]      = __float2half_rn((q1 * c - q2 * s) * qs);
    qkv[qb + 32] = __float2half_rn((q2 * c + q1 * s) * qs);
    float k1 = __half2float(qkv[kb]), k2 = __half2float(qkv[kb + 32]);
    qkv[kb]      = __float2half_rn(k1 * c - k2 * s);
    qkv[kb + 32] = __float2half_rn(k2 * c + k1 * s);
}

// ---------------------------------------------------------------------------
// Tensor-core fp16 GEMM:  C = A @ B   (fp32 accum)
// 128x128 block tile, BK=32, 4 warps (2x2) of 64x64.
// 4-stage cp.async pipeline, ONE __syncthreads per k-iter.
// Register-level fragment double-buffering: A-frag for fm+1 and B-frags for
// the next kk prefetched while the current 8-MMA batch issues (hides the
// ~29cyc LDS latency that capped tensor at 53.7% with occ=12.2%).
// Dynamic smem: 4 x (128xAST + 32xBST) fp16 = 75776 B (2 CTAs/SM).
// Epilogues:
//   EPI 1: gelu(acc + bias) -> fp16
//   EPI 2: C = resid + ada[tok, gate_off+n] * (acc [+ bias])   (fp32)
//   EPI 3: fp16(acc)
// ---------------------------------------------------------------------------
#define AST 40    // A smem row stride (fp16): 32 + 8 pad
#define BST 136   // B smem row stride (fp16): 128 + 8 pad
#define STG_ELEMS (128 * AST + 32 * BST)        // 9472 fp16
#define GEMM_SMEM (4 * STG_ELEMS * 2)           // 75776 B

template<int EPI>
__global__ void __launch_bounds__(128, 2)
mma_gemm(const h16* __restrict__ A, const h16* __restrict__ B,
         float* __restrict__ C, h16* __restrict__ Ch,
         int M, int N, int K,
         const float* __restrict__ bias, const float* __restrict__ resid,
         const float* __restrict__ ada, int gate_off)
{
    extern __shared__ __align__(16) h16 smem[];

    int tid  = threadIdx.x;
    int lane = tid & 31;
    int wid  = tid >> 5;                 // 0..3
    int wm   = (wid >> 1) * 64;          // warp row: 0 or 64
    int wn   = (wid & 1)  * 64;          // warp col: 0 or 64
    int m0   = blockIdx.y * 128;
    int n0   = blockIdx.x * 128;

    uint32_t base = (uint32_t)__cvta_generic_to_shared(smem);
    uint32_t aS[4], bS[4];
#pragma unroll
    for (int s = 0; s < 4; s++) {
        aS[s] = base + s * (STG_ELEMS * 2);
        bS[s] = aS[s] + 128 * AST * 2;
    }

    float acc[4][8][4];                  // [m-frag 16][n-frag 8][regs]
#pragma unroll
    for (int i = 0; i < 4; i++)
#pragma unroll
        for (int j = 0; j < 8; j++)
#pragma unroll
            for (int r = 0; r < 4; r++) acc[i][j][r] = 0.f;

    const int kiters = K / 32;

    auto issue = [&](int ki) {
        int k0  = ki * 32;
        int buf = ki & 3;
#pragma unroll
        for (int li = 0; li < 4; li++) {
            int f = tid + li * 128;          // 0..511
            int row = f >> 2, cc = f & 3;    // A: 128 rows x 4 chunks
            cp16(aS[buf] + (row * AST + cc * 8) * 2,
                 A + (size_t)(m0 + row) * K + k0 + cc * 8);
        }
#pragma unroll
        for (int li = 0; li < 4; li++) {
            int f = tid + li * 128;
            int row = f >> 4, cc = f & 15;   // B: 32 rows x 16 chunks
            cp16(bS[buf] + (row * BST + cc * 8) * 2,
                 B + (size_t)(k0 + row) * N + n0 + cc * 8);
        }
        asm volatile("cp.async.commit_group;");
    };

    issue(0);
    if (kiters > 1) issue(1);
    if (kiters > 2) issue(2);

    int lr = lane & 15;                  // ldmatrix row-select lane bits
    int lc = (lane >> 4) * 8;

    for (int i = 0; i < kiters; i++) {
        if (i + 1 >= kiters)      asm volatile("cp.async.wait_group 0;");
        else if (i + 2 >= kiters) asm volatile("cp.async.wait_group 1;");
        else                      asm volatile("cp.async.wait_group 2;");
        __syncthreads();
        if (i + 3 < kiters) issue(i + 3);   // writes buf (i+3)&3 == (i-1)&3; its
                                            // readers finished before this barrier
        int buf = i & 3;
        uint32_t aB = aS[buf], bB = bS[buf];

        // --- register-pipelined inner product over kk = 0, 16 ---
        uint32_t bfr[2][4][4];               // [kk-buf][n-chunk][frag]
        uint32_t afr[2][4];                  // [parity][frag]

        // preload B frags for kk=0 and A frag (kk=0, fm=0)
#pragma unroll
        for (int j4 = 0; j4 < 4; j4++)
            ldmBt(bfr[0][j4], bB + ((lr) * BST + lc + wn + 16 * j4) * 2);
        ldmA(afr[0], aB + ((wm + lr) * AST + lc) * 2);

#pragma unroll
        for (int kki = 0; kki < 2; kki++) {
            int kk = kki * 16;
#pragma unroll
            for (int fm = 0; fm < 4; fm++) {
                int cur = (kki * 4 + fm) & 1;
                // prefetch next A fragment
                if (fm < 3)
                    ldmA(afr[cur ^ 1],
                         aB + ((wm + 16 * (fm + 1) + lr) * AST + kk + lc) * 2);
                else if (kki == 0)
                    ldmA(afr[cur ^ 1],
                         aB + ((wm + lr) * AST + 16 + lc) * 2);
                // prefetch kk=16 B frags early, behind kk=0/fm=0's MMAs
                if (kki == 0 && fm == 0) {
#pragma unroll
                    for (int j4 = 0; j4 < 4; j4++)
                        ldmBt(bfr[1][j4],
                              bB + ((16 + lr) * BST + lc + wn + 16 * j4) * 2);
                }
#pragma unroll
                for (int j4 = 0; j4 < 4; j4++) {
                    mma16816(acc[fm][2 * j4],     afr[cur], bfr[kki][j4][0], bfr[kki][j4][1]);
                    mma16816(acc[fm][2 * j4 + 1], afr[cur], bfr[kki][j4][2], bfr[kki][j4][3]);
                }
            }
        }
    }

    int r0 = lane >> 2;
    int c0 = 2 * (lane & 3);
#pragma unroll
    for (int fm = 0; fm < 4; fm++) {
#pragma unroll
        for (int fn = 0; fn < 8; fn++) {
            float* d = acc[fm][fn];
            int row = m0 + wm + 16 * fm + r0;
            int col = n0 + wn + 8 * fn + c0;
#pragma unroll
            for (int half = 0; half < 2; half++) {
                int rr = row + 8 * half;
                float v0 = d[2 * half], v1 = d[2 * half + 1];
                size_t off = (size_t)rr * N + col;
                if (EPI == 1) {
                    float gl0 = gelu_tanh(v0 + bias[col]);
                    float gl1 = gelu_tanh(v1 + bias[col + 1]);
                    *(h162*)&Ch[off] = __floats2half2_rn(gl0, gl1);
                } else if (EPI == 2) {
                    float t0 = v0, t1 = v1;
                    if (bias) { t0 += bias[col]; t1 += bias[col + 1]; }
                    int b6 = (rr >> 10) * ADA_N;
                    float g0 = ada[b6 + gate_off + col];
                    float g1 = ada[b6 + gate_off + col + 1];
                    float o0 = resid[off]     + g0 * t0;
                    float o1 = resid[off + 1] + g1 * t1;
                    *(float2*)&C[off] = make_float2(o0, o1);
                } else {  // EPI == 3: plain fp16
                    *(h162*)&Ch[off] = __floats2half2_rn(v0, v1);
                }
            }
        }
    }
}

// ---------------------------------------------------------------------------
// Tensor-core flash attention (fp16 mma, fp32 softmax/accum, exp2 domain).
// One block = 128 query rows of one (b, h); 8 warps x 16 rows.
// 16 KV tiles of 64 keys, double-buffered via cp.async.
// Dynamic smem: (128 + 4*64) * QST fp16 = 55296 B (2 CTAs/SM).
// ---------------------------------------------------------------------------
#define QST 72   // smem row stride (fp16): 64 + 8 pad
#define ATTN_SMEM ((128 + 4 * 64) * QST * 2)    // 55296 B

__global__ void __launch_bounds__(256)
attn_mma_kernel(const h16* __restrict__ qkv, h16* __restrict__ oattn)
{
    extern __shared__ __align__(16) h16 asmem[];
    h16* Qs    = asmem;                   // [128][QST]
    h16* Ks[2] = {asmem + 128 * QST, asmem + (128 + 64) * QST};
    h16* Vs[2] = {asmem + (128 + 128) * QST, asmem + (128 + 192) * QST};

    int tid  = threadIdx.x;
    int lane = tid & 31;
    int w    = tid >> 5;                  // 0..7
    int bh   = blockIdx.y;
    int b    = bh >> 4;
    int h    = bh & 15;
    int q0   = b * SEQ_L + blockIdx.x * 128;
    int kb0  = b * SEQ_L;
    int cb   = h * HEAD_DIM;

    uint32_t sQ = (uint32_t)__cvta_generic_to_shared(Qs);
    uint32_t sK[2] = {(uint32_t)__cvta_generic_to_shared(Ks[0]),
                      (uint32_t)__cvta_generic_to_shared(Ks[1])};
    uint32_t sV[2] = {(uint32_t)__cvta_generic_to_shared(Vs[0]),
                      (uint32_t)__cvta_generic_to_shared(Vs[1])};

    auto issue_kv = [&](int tile, int buf) {
        const h16* kp = qkv + (size_t)(kb0 + tile * 64) * QKV_N + DIM + cb;
        const h16* vp = qkv + (size_t)(kb0 + tile * 64) * QKV_N + 2 * DIM + cb;
#pragma unroll
        for (int i = 0; i < 2; i++) {
            int f = tid + i * 256;            // 0..511 (64 rows x 8 chunks)
            int row = f >> 3, c = f & 7;
            cp16(sK[buf] + (row * QST + c * 8) * 2, kp + (size_t)row * QKV_N + c * 8);
            cp16(sV[buf] + (row * QST + c * 8) * 2, vp + (size_t)row * QKV_N + c * 8);
        }
        asm volatile("cp.async.commit_group;");
    };

    // Q (128 rows) + first KV tile share commit group 0
    {
        const h16* qp = qkv + (size_t)q0 * QKV_N + cb;
#pragma unroll
        for (int i = 0; i < 4; i++) {
            int f = tid + i * 256;            // 0..1023 (128 rows x 8 chunks)
            int row = f >> 3, c = f & 7;
            cp16(sQ + (row * QST + c * 8) * 2, qp + (size_t)row * QKV_N + c * 8);
        }
    }
    issue_kv(0, 0);

    float m0 = -1e30f, m1 = -1e30f, l0 = 0.f, l1 = 0.f;
    float o[8][4];
#pragma unroll
    for (int j = 0; j < 8; j++)
#pragma unroll
        for (int r = 0; r < 4; r++) o[j][r] = 0.f;

    uint32_t aq[4][4];   // Q fragments, loaded once at t==0

    for (int t = 0; t < 16; t++) {
        if (t < 15) {
            issue_kv(t + 1, (t + 1) & 1);
            asm volatile("cp.async.wait_group 1;");
        } else {
            asm volatile("cp.async.wait_group 0;");
        }
        __syncthreads();

        if (t == 0) {
#pragma unroll
            for (int kk = 0; kk < 4; kk++)
                ldmA(aq[kk], sQ + ((16 * w + (lane & 15)) * QST + kk * 16
                                   + (lane >> 4) * 8) * 2);
        }

        int buf = t & 1;
        uint32_t bk = sK[buf], bv = sV[buf];

        // S = Q @ K^T
        float s[8][4];
#pragma unroll
        for (int j = 0; j < 8; j++)
#pragma unroll
            for (int r = 0; r < 4; r++) s[j][r] = 0.f;

#pragma unroll
        for (int kg4 = 0; kg4 < 4; kg4++) {
#pragma unroll
            for (int kk = 0; kk < 4; kk++) {
                uint32_t kf[4];
                ldmA(kf, bk + ((16 * kg4 + (lane & 7) + 8 * ((lane >> 3) & 1)) * QST
                               + kk * 16 + (lane >> 4) * 8) * 2);
                mma16816(s[2 * kg4],     aq[kk], kf[0], kf[2]);
                mma16816(s[2 * kg4 + 1], aq[kk], kf[1], kf[3]);
            }
        }

        // online softmax in exp2 domain (log2e folded into Q scale)
        float tm0 = -1e30f, tm1 = -1e30f;
#pragma unroll
        for (int j = 0; j < 8; j++) {
            tm0 = fmaxf(tm0, fmaxf(s[j][0], s[j][1]));
            tm1 = fmaxf(tm1, fmaxf(s[j][2], s[j][3]));
        }
        tm0 = fmaxf(tm0, __shfl_xor_sync(0xffffffffu, tm0, 1));
        tm0 = fmaxf(tm0, __shfl_xor_sync(0xffffffffu, tm0, 2));
        tm1 = fmaxf(tm1, __shfl_xor_sync(0xffffffffu, tm1, 1));
        tm1 = fmaxf(tm1, __shfl_xor_sync(0xffffffffu, tm1, 2));

        float mn0 = fmaxf(m0, tm0), mn1 = fmaxf(m1, tm1);
        float f0 = exp2f(m0 - mn0), f1 = exp2f(m1 - mn1);
        m0 = mn0; m1 = mn1;

        float ps0 = 0.f, ps1 = 0.f;
#pragma unroll
        for (int j = 0; j < 8; j++) {
            s[j][0] = exp2f(s[j][0] - mn0);
            s[j][1] = exp2f(s[j][1] - mn0);
            s[j][2] = exp2f(s[j][2] - mn1);
            s[j][3] = exp2f(s[j][3] - mn1);
            ps0 += s[j][0] + s[j][1];
            ps1 += s[j][2] + s[j][3];
        }
        ps0 += __shfl_xor_sync(0xffffffffu, ps0, 1);
        ps0 += __shfl_xor_sync(0xffffffffu, ps0, 2);
        ps1 += __shfl_xor_sync(0xffffffffu, ps1, 1);
        ps1 += __shfl_xor_sync(0xffffffffu, ps1, 2);
        l0 = l0 * f0 + ps0;
        l1 = l1 * f1 + ps1;

#pragma unroll
        for (int j = 0; j < 8; j++) {
            o[j][0] *= f0; o[j][1] *= f0;
            o[j][2] *= f1; o[j][3] *= f1;
        }

        // O += P @ V  (P repacked from S fragments; C-frag layout == A-frag layout)
#pragma unroll
        for (int j4 = 0; j4 < 4; j4++) {
            uint32_t a[4];
            a[0] = packh(s[2 * j4][0],     s[2 * j4][1]);
            a[1] = packh(s[2 * j4][2],     s[2 * j4][3]);
            a[2] = packh(s[2 * j4 + 1][0], s[2 * j4 + 1][1]);
            a[3] = packh(s[2 * j4 + 1][2], s[2 * j4 + 1][3]);
#pragma unroll
            for (int q2 = 0; q2 < 4; q2++) {
                uint32_t vf[4];
                ldmBt(vf, bv + ((16 * j4 + (lane & 15)) * QST + q2 * 16
                                + (lane >> 4) * 8) * 2);
                mma16816(o[2 * q2],     a, vf[0], vf[1]);
                mma16816(o[2 * q2 + 1], a, vf[2], vf[3]);
            }
        }
        __syncthreads();   // all reads of buf done before it is re-filled
    }

    // epilogue: divide by l, write fp16
    float inv0 = 1.0f / l0, inv1 = 1.0f / l1;
    int r0 = lane >> 2, c0 = 2 * (lane & 3);
    int row0 = q0 + 16 * w + r0;
#pragma unroll
    for (int j = 0; j < 8; j++) {
        int col = cb + 8 * j + c0;
        size_t off0 = (size_t)row0 * DIM + col;
        size_t off1 = (size_t)(row0 + 8) * DIM + col;
        *(h162*)&oattn[off0] = __floats2half2_rn(o[j][0] * inv0, o[j][1] * inv0);
        *(h162*)&oattn[off1] = __floats2half2_rn(o[j][2] * inv1, o[j][3] * inv1);
    }
}

// ---------------------------------------------------------------------------
// Host-side launch
// ---------------------------------------------------------------------------
extern "C" void kernel_launch(void* const* d_in, const int* in_sizes, int n_in,
                              void* d_out, int out_size)
{
    const float* x     = (const float*)d_in[0];
    const float* cosp  = (const float*)d_in[3];
    const float* sinp  = (const float*)d_in[4];
    const float* c     = (const float*)d_in[6];
    const float* ln1_w = (const float*)d_in[7];
    const float* Wq    = (const float*)d_in[8];
    const float* Wk    = (const float*)d_in[9];
    const float* Wv    = (const float*)d_in[10];
    const float* Wo    = (const float*)d_in[11];
    const float* ln2_w = (const float*)d_in[12];
    const float* W1    = (const float*)d_in[13];
    const float* b1    = (const float*)d_in[14];
    const float* W2    = (const float*)d_in[15];
    const float* b2    = (const float*)d_in[16];
    const float* ada_w = (const float*)d_in[17];
    const float* ada_b = (const float*)d_in[18];
    float*       out   = (float*)d_out;

    float* pada;
    h16 *ph, *pqkv, *pattn, *pmlp;
    h16 *wqkv, *wo, *w1, *w2;
    cudaGetSymbolAddress((void**)&pada,  g_ada);
    cudaGetSymbolAddress((void**)&ph,    g_h);
    cudaGetSymbolAddress((void**)&pqkv,  g_qkv);
    cudaGetSymbolAddress((void**)&pattn, g_attn);
    cudaGetSymbolAddress((void**)&pmlp,  g_mlp);
    cudaGetSymbolAddress((void**)&wqkv,  g_wqkv);
    cudaGetSymbolAddress((void**)&wo,    g_wo);
    cudaGetSymbolAddress((void**)&w1,    g_w1);
    cudaGetSymbolAddress((void**)&w2,    g_w2);

    cudaFuncSetAttribute(mma_gemm<1>, cudaFuncAttributeMaxDynamicSharedMemorySize, GEMM_SMEM);
    cudaFuncSetAttribute(mma_gemm<2>, cudaFuncAttributeMaxDynamicSharedMemorySize, GEMM_SMEM);
    cudaFuncSetAttribute(mma_gemm<3>, cudaFuncAttributeMaxDynamicSharedMemorySize, GEMM_SMEM);
    cudaFuncSetAttribute(attn_mma_kernel, cudaFuncAttributeMaxDynamicSharedMemorySize, ATTN_SMEM);

    // 0. convert all weights to fp16 in one launch (QKV concatenated)
    conv_all<<<12288, 256>>>(Wq, Wk, Wv, Wo, W1, W2, wqkv, wo, w1, w2);

    // 1. adaLN
    ada_kernel<<<dim3(ADA_N / 256, BATCH), 256>>>(c, ada_w, ada_b, pada);

    // 2. h = LN(x) * (1 + sc_msa) + sh_msa -> fp16
    ln_mod_kernel<<<T_TOK, 256>>>(x, ln1_w, pada, /*sh*/0, /*sc*/DIM, ph);

    // 3. fused QKV projection (N=3072) -> fp16 qkv buffer
    mma_gemm<3><<<dim3(QKV_N / 128, T_TOK / 128), 128, GEMM_SMEM>>>(ph, wqkv,
        nullptr, pqkv, T_TOK, QKV_N, DIM, nullptr, nullptr, nullptr, 0);

    // 4. RoPE in place on q,k columns (q scaled by log2e/8)
    rope_kernel<<<(T_TOK * N_HEADS * 32) / 256, 256>>>(pqkv, cosp, sinp);

    // 5. tensor-core flash attention (128-row q tiles) -> fp16
    attn_mma_kernel<<<dim3(SEQ_L / 128, BATCH * N_HEADS), 256, ATTN_SMEM>>>(pqkv,
                                                                            pattn);

    // 6. x2 = x + g_msa * (attn @ Wo)   (x2 in d_out)
    mma_gemm<2><<<dim3(DIM / 128, T_TOK / 128), 128, GEMM_SMEM>>>(pattn, wo,
        out, nullptr, T_TOK, DIM, DIM, nullptr, x, pada, /*g_msa*/2 * DIM);

    // 7. h2 = LN(x2) * (1 + sc_mlp) + sh_mlp -> fp16
    ln_mod_kernel<<<T_TOK, 256>>>(out, ln2_w, pada, /*sh*/3 * DIM, /*sc*/4 * DIM, ph);

    // 8. mlp1 = gelu(h2 @ W1 + b1) -> fp16
    mma_gemm<1><<<dim3(HID / 128, T_TOK / 128), 128, GEMM_SMEM>>>(ph, w1,
        nullptr, pmlp, T_TOK, HID, DIM, b1, nullptr, nullptr, 0);

    // 9. out = x2 + g_mlp * (mlp1 @ W2 + b2)  (in-place on d_out)
    mma_gemm<2><<<dim3(DIM / 128, T_TOK / 128), 128, GEMM_SMEM>>>(pmlp, w2,
        out, nullptr, T_TOK, DIM, HID, b2, out, pada, /*g_mlp*/5 * DIM);
}